// round 2
// baseline (speedup 1.0000x reference)
#include <cuda_runtime.h>
#include <math.h>

// Problem constants (fixed by the dataset)
constexpr int C   = 32;
constexpr int N_H = 40000, D_H = 16;
constexpr int N_O = 20000, D_O = 48;

constexpr int WPB   = 8;          // warps per block
constexpr int BLOCK = WPB * 32;   // 256 threads
constexpr int NB_O  = N_O / WPB;  // 2500 blocks (O first: heavier work)
constexpr int NB_H  = N_H / WPB;  // 5000 blocks

// Padded triangular size: each row i of the folded-symmetric matrix has (i+1)
// entries, padded up to a multiple of 4 floats (zero-filled) so the inner loop
// can use aligned float4 shared loads with no guards.
template <int D>
__host__ __device__ constexpr int paddedTri() {
    int s = 0;
    for (int i = 0; i < D; i++) s += (i + 4) & ~3;
    return s;
}
// D=48 -> 1248 floats (4992 B), D=16 -> 160 floats

// Fill shared packed matrix: Tp[i][i] = S_ii, Tp[i][j<i] = 2*S_ij, pad = 0.
template <int D>
__device__ void fillS(const float* __restrict__ S, float* Sp) {
    constexpr int P = paddedTri<D>();
    for (int k = threadIdx.x; k < P; k += BLOCK) Sp[k] = 0.0f;
    __syncthreads();
    for (int k = threadIdx.x; k < D * D; k += BLOCK) {
        int i = k / D;
        int j = k - i * D;
        if (j <= i) {
            int off = 0;
            for (int t = 0; t < i; t++) off += (t + 4) & ~3;
            Sp[off + j] = S[k] * (j == i ? 1.0f : 2.0f);
        }
    }
    __syncthreads();
}

// One warp processes one atom; lane = channel.
// acc_c = sum_i y_ic * (sum_{j<=i} Tp_ij * y_jc)  ==  y_c^T S y_c
template <int D>
__device__ __forceinline__ void processAtom(const float* __restrict__ x,
                                            float* __restrict__ out,
                                            const float* __restrict__ Sp,
                                            int baseRow, int lane) {
    const int base = baseRow * C + lane;

    float y[D];
#pragma unroll
    for (int i = 0; i < D; i++) y[i] = __ldg(x + base + i * C);

    float acc = 0.0f;
    int off = 0;  // compile-time after full unroll
#pragma unroll
    for (int i = 0; i < D; i++) {
        const int nc = i / 4 + 1;  // number of float4 chunks in row i
        float u0 = 0.0f, u1 = 0.0f;
#pragma unroll
        for (int jc = 0; jc < nc; jc++) {
            float4 s4 = *reinterpret_cast<const float4*>(Sp + off + 4 * jc);
            if ((jc & 1) == 0) {
                u0 = fmaf(s4.x, y[4 * jc + 0], u0);
                u0 = fmaf(s4.y, y[4 * jc + 1], u0);
                u0 = fmaf(s4.z, y[4 * jc + 2], u0);
                u0 = fmaf(s4.w, y[4 * jc + 3], u0);
            } else {
                u1 = fmaf(s4.x, y[4 * jc + 0], u1);
                u1 = fmaf(s4.y, y[4 * jc + 1], u1);
                u1 = fmaf(s4.z, y[4 * jc + 2], u1);
                u1 = fmaf(s4.w, y[4 * jc + 3], u1);
            }
        }
        acc = fmaf(y[i], u0 + u1, acc);
        off += (i + 4) & ~3;
    }

    const float inv = 1.0f / (sqrtf(acc) + 1e-6f);
#pragma unroll
    for (int i = 0; i < D; i++) out[base + i * C] = y[i] * inv;
}

__global__ __launch_bounds__(BLOCK) void l2norm_kernel(
    const float* __restrict__ x,
    const float* __restrict__ S_H,
    const float* __restrict__ S_O,
    const int* __restrict__ idx_H,
    const int* __restrict__ idx_O,
    float* __restrict__ out) {
    __shared__ __align__(16) float Sp[paddedTri<D_O>()];

    const int warp = threadIdx.x >> 5;
    const int lane = threadIdx.x & 31;

    if (blockIdx.x < NB_O) {
        fillS<D_O>(S_O, Sp);
        const int atom    = blockIdx.x * WPB + warp;
        const int baseRow = __ldg(idx_O + atom * D_O);
        processAtom<D_O>(x, out, Sp, baseRow, lane);
    } else {
        fillS<D_H>(S_H, Sp);
        const int atom    = (blockIdx.x - NB_O) * WPB + warp;
        const int baseRow = __ldg(idx_H + atom * D_H);
        processAtom<D_H>(x, out, Sp, baseRow, lane);
    }
}

extern "C" void kernel_launch(void* const* d_in, const int* in_sizes, int n_in,
                              void* d_out, int out_size) {
    const float* x     = (const float*)d_in[0];
    const float* S_H   = (const float*)d_in[1];
    const float* S_O   = (const float*)d_in[2];
    const int*   idx_H = (const int*)d_in[3];
    const int*   idx_O = (const int*)d_in[4];
    float* out = (float*)d_out;

    l2norm_kernel<<<NB_O + NB_H, BLOCK>>>(x, S_H, S_O, idx_H, idx_O, out);
}

// round 3
// speedup vs baseline: 1.0574x; 1.0574x over previous
#include <cuda_runtime.h>
#include <math.h>

// Problem constants (fixed by the dataset)
constexpr int C   = 32;
constexpr int N_H = 40000, D_H = 16;
constexpr int N_O = 20000, D_O = 48;

constexpr int WPB   = 8;          // warps per block
constexpr int BLOCK = WPB * 32;   // 256 threads
// Each warp processes TWO atoms (lane<16 -> atom A, lane>=16 -> atom B),
// each lane owns a contiguous channel PAIR handled with packed f32x2 math.
constexpr int NB_O = N_O / (2 * WPB);  // 1250
constexpr int NB_H = N_H / (2 * WPB);  // 2500

typedef unsigned long long u64;

// ---- packed f32x2 helpers (Blackwell FFMA2 path, PTX-only) ----
__device__ __forceinline__ u64 fma2(u64 a, u64 b, u64 c) {
    u64 d;
    asm("fma.rn.f32x2 %0, %1, %2, %3;" : "=l"(d) : "l"(a), "l"(b), "l"(c));
    return d;
}
__device__ __forceinline__ u64 add2(u64 a, u64 b) {
    u64 d;
    asm("add.rn.f32x2 %0, %1, %2;" : "=l"(d) : "l"(a), "l"(b));
    return d;
}
__device__ __forceinline__ u64 mul2(u64 a, u64 b) {
    u64 d;
    asm("mul.rn.f32x2 %0, %1, %2;" : "=l"(d) : "l"(a), "l"(b));
    return d;
}
__device__ __forceinline__ u64 pack2(float lo, float hi) {
    u64 d;
    asm("mov.b64 %0, {%1, %2};" : "=l"(d) : "r"(__float_as_uint(lo)), "r"(__float_as_uint(hi)));
    return d;
}

// Folded-symmetric triangular layout, each entry DUPLICATED (s,s) as one u64.
// Row i: (i+1) entries padded to a multiple of 2 (16B chunks of 2 entries).
__host__ __device__ constexpr int rowPad(int i) { return (i + 2) & ~1; }
template <int D>
__host__ __device__ constexpr int triTot() {
    int s = 0;
    for (int t = 0; t < D; t++) s += rowPad(t);
    return s;
}
// D=48 -> 1200 u64 (9.6KB), D=16 -> 144 u64 (1.15KB)

template <int D>
__device__ void fillS2(const float* __restrict__ S, u64* Sp) {
    constexpr int TOT = triTot<D>();
    for (int k = threadIdx.x; k < TOT; k += BLOCK) Sp[k] = 0ull;
    __syncthreads();
    for (int k = threadIdx.x; k < D * D; k += BLOCK) {
        int i = k / D;
        int j = k - i * D;
        if (j <= i) {
            int off = 0;
            for (int t = 0; t < i; t++) off += rowPad(t);
            float v = S[k] * (i == j ? 1.0f : 2.0f);
            unsigned int u = __float_as_uint(v);
            Sp[off + j] = ((u64)u << 32) | u;
        }
    }
    __syncthreads();
}

// One warp = 2 atoms; lane = (half, channel-pair). All math packed f32x2.
template <int D>
__device__ __forceinline__ void processAtomPair(const float* __restrict__ x,
                                                float* __restrict__ out,
                                                const u64* __restrict__ Sp,
                                                const int* __restrict__ idx,
                                                int atomPair, int lane) {
    const int half = lane >> 4;    // which atom of the pair
    const int cp   = lane & 15;    // channel pair index (channels 2cp, 2cp+1)
    const int atom = atomPair * 2 + half;
    const int baseRow = __ldg(idx + atom * D);

    const u64* xp = reinterpret_cast<const u64*>(x) + (size_t)baseRow * (C / 2) + cp;

    u64 y[D];
#pragma unroll
    for (int i = 0; i < D; i++) y[i] = __ldg(xp + i * (C / 2));

    u64 acc = 0ull;
    int off = 0;  // constant-folds after full unroll
#pragma unroll
    for (int i = 0; i < D; i++) {
        const int nc = i / 2 + 1;  // 16B chunks (2 dup-entries each) in row i
        u64 u0 = 0ull, u1 = 0ull;
        const ulonglong2* row = reinterpret_cast<const ulonglong2*>(Sp + off);
#pragma unroll
        for (int jc = 0; jc < nc; jc++) {
            ulonglong2 s2 = row[jc];                // LDS.128 broadcast
            u0 = fma2(s2.x, y[2 * jc + 0], u0);
            u1 = fma2(s2.y, y[2 * jc + 1], u1);
        }
        acc = fma2(y[i], add2(u0, u1), acc);
        off += rowPad(i);
    }

    const float a0 = __uint_as_float((unsigned int)acc);
    const float a1 = __uint_as_float((unsigned int)(acc >> 32));
    const u64 inv  = pack2(1.0f / (sqrtf(a0) + 1e-6f),
                           1.0f / (sqrtf(a1) + 1e-6f));

    u64* op = reinterpret_cast<u64*>(out) + (size_t)baseRow * (C / 2) + cp;
#pragma unroll
    for (int i = 0; i < D; i++) op[i * (C / 2)] = mul2(y[i], inv);
}

__global__ __launch_bounds__(BLOCK, 2) void l2norm_O(
    const float* __restrict__ x, const float* __restrict__ S_O,
    const int* __restrict__ idx_O, float* __restrict__ out) {
    __shared__ __align__(16) u64 Sp[triTot<D_O>()];
    fillS2<D_O>(S_O, Sp);
    const int warp = threadIdx.x >> 5;
    const int lane = threadIdx.x & 31;
    processAtomPair<D_O>(x, out, Sp, idx_O, blockIdx.x * WPB + warp, lane);
}

__global__ __launch_bounds__(BLOCK) void l2norm_H(
    const float* __restrict__ x, const float* __restrict__ S_H,
    const int* __restrict__ idx_H, float* __restrict__ out) {
    __shared__ __align__(16) u64 Sp[triTot<D_H>()];
    fillS2<D_H>(S_H, Sp);
    const int warp = threadIdx.x >> 5;
    const int lane = threadIdx.x & 31;
    processAtomPair<D_H>(x, out, Sp, idx_H, blockIdx.x * WPB + warp, lane);
}

extern "C" void kernel_launch(void* const* d_in, const int* in_sizes, int n_in,
                              void* d_out, int out_size) {
    const float* x     = (const float*)d_in[0];
    const float* S_H   = (const float*)d_in[1];
    const float* S_O   = (const float*)d_in[2];
    const int*   idx_H = (const int*)d_in[3];
    const int*   idx_O = (const int*)d_in[4];
    float* out = (float*)d_out;

    l2norm_O<<<NB_O, BLOCK>>>(x, S_O, idx_O, out);
    l2norm_H<<<NB_H, BLOCK>>>(x, S_H, idx_H, out);
}